// round 2
// baseline (speedup 1.0000x reference)
#include <cuda_runtime.h>
#include <cuda_bf16.h>
#include <cstddef>

// ---------------------------------------------------------------------------
// Problem constants (B=1)
// ---------------------------------------------------------------------------
#define S_   2048
#define H_   4096
#define NH_  32
#define DN_  128
#define DR_  64
#define DV_  128
#define QK_  192      // DN + DR
#define RQ_  1536
#define RKV_ 512
#define CKV_ 576      // RKV + DR

// ---------------------------------------------------------------------------
// Device scratch (allocation-free rule: static __device__ arrays)
// ---------------------------------------------------------------------------
__device__ float g_cq  [S_ * RQ_];          // hs @ q_a_w^T
__device__ float g_ckv [S_ * CKV_];         // hs @ kv_a_w^T
__device__ float g_qn  [S_ * RQ_];          // rmsnorm(cq)
__device__ float g_kvn [S_ * RKV_];         // rmsnorm(ckv[:, :512])
__device__ float g_q   [S_ * (NH_ * QK_)];  // qn @ q_b_w^T          (2048 x 6144)
__device__ float g_kv  [S_ * (NH_ * 256)];  // kvn @ kv_b_w^T        (2048 x 8192)
__device__ float g_Q   [NH_ * S_ * QK_];    // assembled Q (roped)
__device__ float g_K   [NH_ * S_ * QK_];    // assembled K (roped)
__device__ float g_attn[S_ * (NH_ * DV_)];  // attention output (2048 x 4096)

// ---------------------------------------------------------------------------
// Generic fp32 GEMM:  C[M,N] = A[M,K] @ B[N,K]^T
// 128x128 tile, BK=8, 256 threads, 8x8 micro-tile per thread.
// Assumes: M % 128 == 0, K % 8 == 0, N % 8 == 0 (N may be non-mult of 128).
// ---------------------------------------------------------------------------
__global__ __launch_bounds__(256)
void gemm_nt(const float* __restrict__ A, const float* __restrict__ B,
             float* __restrict__ C, int M, int N, int K) {
    __shared__ float As[8][128];
    __shared__ float Bs[8][128];

    const int tid = threadIdx.x;
    const int tx  = tid & 15;     // col group -> cols tx*8 .. tx*8+7
    const int ty  = tid >> 4;     // row group -> rows ty*8 .. ty*8+7
    const int m0  = blockIdx.y * 128;
    const int n0  = blockIdx.x * 128;

    float acc[8][8];
#pragma unroll
    for (int i = 0; i < 8; i++)
#pragma unroll
        for (int j = 0; j < 8; j++) acc[i][j] = 0.f;

    const int lr = tid >> 1;          // 0..127 (tile row)
    const int lc = (tid & 1) * 4;     // 0 or 4 (k offset)
    const float* Arow = A + (size_t)(m0 + lr) * K + lc;
    const float* Brow = B + (size_t)(n0 + lr) * K + lc;
    const bool bvalid = (n0 + lr) < N;

    for (int k0 = 0; k0 < K; k0 += 8) {
        float4 av = *(const float4*)(Arow + k0);
        float4 bv = make_float4(0.f, 0.f, 0.f, 0.f);
        if (bvalid) bv = *(const float4*)(Brow + k0);
        As[lc + 0][lr] = av.x; As[lc + 1][lr] = av.y;
        As[lc + 2][lr] = av.z; As[lc + 3][lr] = av.w;
        Bs[lc + 0][lr] = bv.x; Bs[lc + 1][lr] = bv.y;
        Bs[lc + 2][lr] = bv.z; Bs[lc + 3][lr] = bv.w;
        __syncthreads();

#pragma unroll
        for (int kk = 0; kk < 8; kk++) {
            float4 a0 = *(const float4*)&As[kk][ty * 8];
            float4 a1 = *(const float4*)&As[kk][ty * 8 + 4];
            float4 b0 = *(const float4*)&Bs[kk][tx * 8];
            float4 b1 = *(const float4*)&Bs[kk][tx * 8 + 4];
            float a[8] = {a0.x, a0.y, a0.z, a0.w, a1.x, a1.y, a1.z, a1.w};
            float b[8] = {b0.x, b0.y, b0.z, b0.w, b1.x, b1.y, b1.z, b1.w};
#pragma unroll
            for (int i = 0; i < 8; i++)
#pragma unroll
                for (int j = 0; j < 8; j++) acc[i][j] += a[i] * b[j];
        }
        __syncthreads();
    }

#pragma unroll
    for (int i = 0; i < 8; i++) {
        int r  = m0 + ty * 8 + i;
        int cb = n0 + tx * 8;
        if (cb < N) {   // N % 8 == 0 and cb % 8 == 0 -> whole 8-wide row valid
            float4 o0 = make_float4(acc[i][0], acc[i][1], acc[i][2], acc[i][3]);
            float4 o1 = make_float4(acc[i][4], acc[i][5], acc[i][6], acc[i][7]);
            *(float4*)&C[(size_t)r * N + cb]     = o0;
            *(float4*)&C[(size_t)r * N + cb + 4] = o1;
        }
    }
}

// ---------------------------------------------------------------------------
// RMSNorm over first n elems of each row (row stride xstride), fp32.
// ---------------------------------------------------------------------------
__global__ __launch_bounds__(256)
void rmsnorm_kernel(const float* __restrict__ x, const float* __restrict__ w,
                    float* __restrict__ y, int n, int xstride) {
    const int row = blockIdx.x;
    const float* xr = x + (size_t)row * xstride;
    float ss = 0.f;
    for (int i = threadIdx.x; i < n; i += blockDim.x) {
        float v = xr[i];
        ss += v * v;
    }
    __shared__ float red[8];
#pragma unroll
    for (int off = 16; off > 0; off >>= 1) ss += __shfl_xor_sync(0xffffffffu, ss, off);
    if ((threadIdx.x & 31) == 0) red[threadIdx.x >> 5] = ss;
    __syncthreads();
    if (threadIdx.x < 8) {
        float v = red[threadIdx.x];
#pragma unroll
        for (int off = 4; off > 0; off >>= 1) v += __shfl_xor_sync(0x000000ffu, v, off);
        if (threadIdx.x == 0) red[0] = v;
    }
    __syncthreads();
    const float sc = rsqrtf(red[0] / (float)n + 1e-6f);
    float* yr = y + (size_t)row * n;
    for (int i = threadIdx.x; i < n; i += blockDim.x)
        yr[i] = xr[i] * sc * w[i];
}

// ---------------------------------------------------------------------------
// Assemble per-head Q/K with RoPE.
//   Q[h][s][0:128] = q[s][h*192 + 0:128]; Q[h][s][128:192] = rope(q_rot)
//   K[h][s][0:128] = kv[s][h*256 + 0:128]; K[h][s][128:192] = rope(k_rot) (bcast)
// grid (S, NH), 160 threads.
// ---------------------------------------------------------------------------
__global__ __launch_bounds__(160)
void assemble_kernel(const float* __restrict__ q, const float* __restrict__ kv,
                     const float* __restrict__ ckv, const float* __restrict__ freqs,
                     float* __restrict__ Q, float* __restrict__ K) {
    const int s = blockIdx.x, h = blockIdx.y, t = threadIdx.x;
    const size_t qbase  = (size_t)s * (NH_ * QK_) + (size_t)h * QK_;
    const size_t kvbase = (size_t)s * (NH_ * 256) + (size_t)h * 256;
    const size_t Qb = ((size_t)h * S_ + s) * QK_;
    if (t < 128) {
        Q[Qb + t] = q[qbase + t];
        K[Qb + t] = kv[kvbase + t];
    } else {
        const int i = t - 128;              // 0..31 rope pair index
        const float f  = freqs[(size_t)s * (DR_ / 2) + i];
        const float c  = cosf(f);
        const float sn = sinf(f);
        float xr = q[qbase + 128 + 2 * i];
        float xi = q[qbase + 128 + 2 * i + 1];
        Q[Qb + 128 + 2 * i]     = xr * c - xi * sn;
        Q[Qb + 128 + 2 * i + 1] = xr * sn + xi * c;
        float kr = ckv[(size_t)s * CKV_ + RKV_ + 2 * i];
        float ki = ckv[(size_t)s * CKV_ + RKV_ + 2 * i + 1];
        K[Qb + 128 + 2 * i]     = kr * c - ki * sn;
        K[Qb + 128 + 2 * i + 1] = kr * sn + ki * c;
    }
}

// ---------------------------------------------------------------------------
// Causal flash attention, fp32.
// grid (S/64 q-tiles, NH heads), 256 threads.
// Per thread: 4x4 score micro-tile (rows ty+16i, cols tx+16j),
//             4x8 output micro-tile (rows ty+16i, cols tx*8..tx*8+7).
// V is read directly out of the kv_b output (cols h*256+128 .. +255).
// ---------------------------------------------------------------------------
#define KSTR 196   // K smem row stride (pad 192 -> 196: float4-aligned, 2-way max conflict)
#define FLASH_SMEM ((64 * 192 + 64 * KSTR + 64 * 128 + 64 * 64) * 4)

__global__ __launch_bounds__(256)
void flash_kernel(const float* __restrict__ Q, const float* __restrict__ K,
                  const float* __restrict__ kv, float* __restrict__ O) {
    extern __shared__ float sm[];
    float* Qs = sm;                       // 64 x 192
    float* Ks = Qs + 64 * 192;            // 64 x KSTR
    float* Vs = Ks + 64 * KSTR;           // 64 x 128
    float* Ps = Vs + 64 * 128;            // 64 x 64

    const int qt = blockIdx.x, h = blockIdx.y;
    const int tid = threadIdx.x;
    const int tx = tid & 15, ty = tid >> 4;
    const int q0 = qt * 64;
    const float scale = 0.07216878364870323f;   // 1/sqrt(192)

    const float* Qh = Q + ((size_t)h * S_ + q0) * QK_;
    for (int idx = tid; idx < 64 * 192; idx += 256) Qs[idx] = Qh[idx];

    float m_[4], l_[4], acc[4][8];
#pragma unroll
    for (int i = 0; i < 4; i++) {
        m_[i] = -1e30f; l_[i] = 0.f;
#pragma unroll
        for (int j = 0; j < 8; j++) acc[i][j] = 0.f;
    }

    for (int kt = 0; kt <= qt; kt++) {
        const int k0 = kt * 64;
        __syncthreads();   // previous iter's Ks/Vs/Ps reads done
        const float* Kh = K + ((size_t)h * S_ + k0) * QK_;
        for (int idx = tid; idx < 64 * 192; idx += 256) {
            int r = idx / 192, c = idx - r * 192;
            Ks[r * KSTR + c] = Kh[idx];
        }
        for (int idx = tid; idx < 64 * 128; idx += 256) {
            int r = idx >> 7, c = idx & 127;
            Vs[idx] = kv[(size_t)(k0 + r) * (NH_ * 256) + (size_t)h * 256 + 128 + c];
        }
        __syncthreads();

        // ---- scores S = Qs @ Ks^T ----
        float s[4][4];
#pragma unroll
        for (int i = 0; i < 4; i++)
#pragma unroll
            for (int j = 0; j < 4; j++) s[i][j] = 0.f;

        for (int d = 0; d < 192; d += 4) {
            float4 a[4], b[4];
#pragma unroll
            for (int i = 0; i < 4; i++)
                a[i] = *(const float4*)&Qs[(ty + 16 * i) * 192 + d];
#pragma unroll
            for (int j = 0; j < 4; j++)
                b[j] = *(const float4*)&Ks[(tx + 16 * j) * KSTR + d];
#pragma unroll
            for (int i = 0; i < 4; i++)
#pragma unroll
                for (int j = 0; j < 4; j++)
                    s[i][j] += a[i].x * b[j].x + a[i].y * b[j].y
                             + a[i].z * b[j].z + a[i].w * b[j].w;
        }

        // ---- online softmax ----
        const bool diag = (kt == qt);
#pragma unroll
        for (int i = 0; i < 4; i++) {
            const int qg = q0 + ty + 16 * i;
            float rm = -1e30f;
#pragma unroll
            for (int j = 0; j < 4; j++) {
                float v = s[i][j] * scale;
                if (diag && (k0 + tx + 16 * j) > qg) v = -1e30f;
                s[i][j] = v;
                rm = fmaxf(rm, v);
            }
#pragma unroll
            for (int off = 8; off > 0; off >>= 1)
                rm = fmaxf(rm, __shfl_xor_sync(0xffffffffu, rm, off));
            const float mn   = fmaxf(m_[i], rm);
            const float corr = __expf(m_[i] - mn);
            float rs = 0.f;
#pragma unroll
            for (int j = 0; j < 4; j++) {
                float p = __expf(s[i][j] - mn);
                Ps[(ty + 16 * i) * 64 + tx + 16 * j] = p;
                rs += p;
            }
#pragma unroll
            for (int off = 8; off > 0; off >>= 1)
                rs += __shfl_xor_sync(0xffffffffu, rs, off);
            l_[i] = l_[i] * corr + rs;
            m_[i] = mn;
#pragma unroll
            for (int j = 0; j < 8; j++) acc[i][j] *= corr;
        }
        __syncthreads();   // Ps visible to all

        // ---- acc += P @ V ----
#pragma unroll 4
        for (int k = 0; k < 64; k++) {
            float4 v0 = *(const float4*)&Vs[(k << 7) + tx * 8];
            float4 v1 = *(const float4*)&Vs[(k << 7) + tx * 8 + 4];
#pragma unroll
            for (int i = 0; i < 4; i++) {
                float p = Ps[(ty + 16 * i) * 64 + k];
                acc[i][0] += p * v0.x; acc[i][1] += p * v0.y;
                acc[i][2] += p * v0.z; acc[i][3] += p * v0.w;
                acc[i][4] += p * v1.x; acc[i][5] += p * v1.y;
                acc[i][6] += p * v1.z; acc[i][7] += p * v1.w;
            }
        }
    }

    // ---- epilogue: out = acc / l, layout [s][h*128 + c] ----
#pragma unroll
    for (int i = 0; i < 4; i++) {
        const float inv = 1.f / l_[i];
        const int r = q0 + ty + 16 * i;
        float4 o0 = make_float4(acc[i][0] * inv, acc[i][1] * inv,
                                acc[i][2] * inv, acc[i][3] * inv);
        float4 o1 = make_float4(acc[i][4] * inv, acc[i][5] * inv,
                                acc[i][6] * inv, acc[i][7] * inv);
        const size_t ob = (size_t)r * (NH_ * DV_) + (size_t)h * DV_ + tx * 8;
        *(float4*)&O[ob]     = o0;
        *(float4*)&O[ob + 4] = o1;
    }
}

// ---------------------------------------------------------------------------
// kernel_launch
// inputs: 0 hidden_states, 1 freqs, 2 q_a_w, 3 q_a_ln_w, 4 q_b_w,
//         5 kv_a_w, 6 kv_a_ln_w, 7 kv_b_w, 8 o_w     (all float32)
// output: float32 [2048, 4096]
// ---------------------------------------------------------------------------
extern "C" void kernel_launch(void* const* d_in, const int* in_sizes, int n_in,
                              void* d_out, int out_size) {
    (void)in_sizes; (void)n_in; (void)out_size;
    const float* hs       = (const float*)d_in[0];
    const float* freqs    = (const float*)d_in[1];
    const float* q_a_w    = (const float*)d_in[2];
    const float* q_a_ln   = (const float*)d_in[3];
    const float* q_b_w    = (const float*)d_in[4];
    const float* kv_a_w   = (const float*)d_in[5];
    const float* kv_a_ln  = (const float*)d_in[6];
    const float* kv_b_w   = (const float*)d_in[7];
    const float* o_w      = (const float*)d_in[8];
    float* out            = (float*)d_out;

    float *cq, *ckv, *qn, *kvn, *q, *kv, *Qp, *Kp, *attn;
    cudaGetSymbolAddress((void**)&cq,   g_cq);
    cudaGetSymbolAddress((void**)&ckv,  g_ckv);
    cudaGetSymbolAddress((void**)&qn,   g_qn);
    cudaGetSymbolAddress((void**)&kvn,  g_kvn);
    cudaGetSymbolAddress((void**)&q,    g_q);
    cudaGetSymbolAddress((void**)&kv,   g_kv);
    cudaGetSymbolAddress((void**)&Qp,   g_Q);
    cudaGetSymbolAddress((void**)&Kp,   g_K);
    cudaGetSymbolAddress((void**)&attn, g_attn);

    const dim3 blk(256);

    // down-projections
    gemm_nt<<<dim3(RQ_ / 128, S_ / 128), blk>>>(hs, q_a_w, cq, S_, RQ_, H_);
    gemm_nt<<<dim3((CKV_ + 127) / 128, S_ / 128), blk>>>(hs, kv_a_w, ckv, S_, CKV_, H_);

    // rmsnorms
    rmsnorm_kernel<<<S_, 256>>>(cq,  q_a_ln,  qn,  RQ_,  RQ_);
    rmsnorm_kernel<<<S_, 256>>>(ckv, kv_a_ln, kvn, RKV_, CKV_);

    // up-projections
    gemm_nt<<<dim3((NH_ * QK_) / 128, S_ / 128), blk>>>(qn,  q_b_w,  q,  S_, NH_ * QK_, RQ_);
    gemm_nt<<<dim3((NH_ * 256) / 128, S_ / 128), blk>>>(kvn, kv_b_w, kv, S_, NH_ * 256, RKV_);

    // RoPE + per-head assembly
    assemble_kernel<<<dim3(S_, NH_), 160>>>(q, kv, ckv, freqs, Qp, Kp);

    // causal flash attention
    cudaFuncSetAttribute(flash_kernel, cudaFuncAttributeMaxDynamicSharedMemorySize,
                         FLASH_SMEM);
    flash_kernel<<<dim3(S_ / 64, NH_), blk, FLASH_SMEM>>>(Qp, Kp, kv, attn);

    // output projection -> d_out
    gemm_nt<<<dim3(H_ / 128, S_ / 128), blk>>>(attn, o_w, out, S_, H_, NH_ * DV_);
}

// round 4
// speedup vs baseline: 1.9039x; 1.9039x over previous
#include <cuda_runtime.h>
#include <cuda_bf16.h>
#include <cstdint>
#include <cstddef>

// ---------------------------------------------------------------------------
// Problem constants (B=1)
// ---------------------------------------------------------------------------
#define S_   2048
#define H_   4096
#define NH_  32
#define DN_  128
#define DR_  64
#define DV_  128
#define QK_  192      // DN + DR
#define RQ_  1536
#define RKV_ 512
#define CKV_ 576      // RKV + DR

// ---------------------------------------------------------------------------
// Device scratch
// ---------------------------------------------------------------------------
__device__ float g_cq  [S_ * RQ_];
__device__ float g_ckv [S_ * CKV_];
__device__ float g_qn  [S_ * RQ_];
__device__ float g_kvn [S_ * RKV_];
__device__ float g_q   [S_ * (NH_ * QK_)];
__device__ float g_kv  [S_ * (NH_ * 256)];
__device__ float g_Q   [NH_ * S_ * QK_];
__device__ float g_K   [NH_ * S_ * QK_];
__device__ float g_attn[S_ * (NH_ * DV_)];

// tf32-rounded operand copies
__device__ float g_hsr  [S_ * H_];
__device__ float g_qaw  [RQ_ * H_];
__device__ float g_kvaw [CKV_ * H_];
__device__ float g_qbw  [NH_ * QK_ * RQ_];
__device__ float g_kvbw [NH_ * 256 * RKV_];
__device__ float g_ow   [H_ * NH_ * DV_];

// ---------------------------------------------------------------------------
// Helpers
// ---------------------------------------------------------------------------
__device__ __forceinline__ float tf32_rna(float x) {
    uint32_t r;
    asm("cvt.rna.tf32.f32 %0, %1;" : "=r"(r) : "f"(x));
    return __uint_as_float(r);
}

__device__ __forceinline__ void cp_async16(uint32_t dst, const void* src, bool pred) {
    int sz = pred ? 16 : 0;
    asm volatile("cp.async.cg.shared.global [%0], [%1], 16, %2;"
                 :: "r"(dst), "l"(src), "r"(sz));
}
__device__ __forceinline__ void cp_commit() {
    asm volatile("cp.async.commit_group;" ::: "memory");
}
template <int N> __device__ __forceinline__ void cp_wait() {
    asm volatile("cp.async.wait_group %0;" :: "n"(N) : "memory");
}

__device__ __forceinline__ uint32_t smem_u32(const void* p) {
    uint32_t a;
    asm("{ .reg .u64 t; cvta.to.shared.u64 t, %1; cvt.u32.u64 %0, t; }"
        : "=r"(a) : "l"(p));
    return a;
}

// ---------------------------------------------------------------------------
// Elementwise tf32 rounding (float4 grid-stride). n % 4 == 0.
// ---------------------------------------------------------------------------
__global__ __launch_bounds__(256)
void round_tf32_kernel(const float* __restrict__ x, float* __restrict__ y, int n) {
    int i = (blockIdx.x * blockDim.x + threadIdx.x) * 4;
    const int stride = gridDim.x * blockDim.x * 4;
    for (; i < n; i += stride) {
        float4 v = *(const float4*)(x + i);
        v.x = tf32_rna(v.x); v.y = tf32_rna(v.y);
        v.z = tf32_rna(v.z); v.w = tf32_rna(v.w);
        *(float4*)(y + i) = v;
    }
}

// ---------------------------------------------------------------------------
// mma.sync tf32 GEMM:  C[M,N] = A[M,K] @ B[N,K]^T
// CTA 128x128x32, 8 warps (4 x 2), warp tile 32x64, 3-stage cp.async.
// Operands MUST be pre-rounded to tf32 (in-MMA truncation is then exact).
// Requires M % 128 == 0, K % 32 == 0, N % 8 == 0.
// ---------------------------------------------------------------------------
#define ASTR 36                                   // padded row stride (floats)
#define MSTAGE_BYTES (2 * 128 * ASTR * 4)         // A + B tile: 36864 B
#define MSTAGES 3
#define MGEMM_SMEM (MSTAGES * MSTAGE_BYTES)       // 110592 B

__global__ __launch_bounds__(256)
void gemm_mma(const float* __restrict__ A, const float* __restrict__ B,
              float* __restrict__ C, int M, int N, int K) {
    extern __shared__ char smem[];
    const uint32_t sb = smem_u32(smem);
    const int tid  = threadIdx.x;
    const int wid  = tid >> 5;
    const int lane = tid & 31;
    const int qr = lane >> 2;        // 0..7
    const int qc = lane & 3;         // 0..3
    const int wm = (wid & 3) * 32;   // warp M offset in tile
    const int wn = (wid >> 2) * 64;  // warp N offset in tile
    const int m0 = blockIdx.y * 128;
    const int n0 = blockIdx.x * 128;

    const int niter = K / 32;

    auto load_stage = [&](int it) {
        const int s = it % MSTAGES;
        const uint32_t abase = sb + s * MSTAGE_BYTES;
        const uint32_t bbase = abase + 128 * ASTR * 4;
        const int k0 = it * 32;
#pragma unroll
        for (int j = 0; j < 4; j++) {               // A: 1024 float4
            int idx = tid + 256 * j;
            int r = idx >> 3, c4 = idx & 7;
            cp_async16(abase + (r * ASTR + c4 * 4) * 4,
                       A + (size_t)(m0 + r) * K + k0 + c4 * 4, true);
        }
#pragma unroll
        for (int j = 0; j < 4; j++) {               // B: 1024 float4
            int idx = tid + 256 * j;
            int r = idx >> 3, c4 = idx & 7;
            bool ok = (n0 + r) < N;
            const float* src = B + (size_t)(n0 + (ok ? r : 0)) * K + k0 + c4 * 4;
            cp_async16(bbase + (r * ASTR + c4 * 4) * 4, src, ok);
        }
        cp_commit();
    };

    float d[2][8][4];
#pragma unroll
    for (int t = 0; t < 2; t++)
#pragma unroll
        for (int n = 0; n < 8; n++)
#pragma unroll
            for (int c = 0; c < 4; c++) d[t][n][c] = 0.f;

    load_stage(0);
    load_stage(1);

    for (int it = 0; it < niter; it++) {
        cp_wait<1>();
        __syncthreads();

        if (it + 2 < niter) load_stage(it + 2);

        const int s = it % MSTAGES;
        const float* As = (const float*)(smem + s * MSTAGE_BYTES);
        const float* Bs = As + 128 * ASTR;

#pragma unroll
        for (int k8 = 0; k8 < 4; k8++) {
            const int k0 = k8 * 8;
            uint32_t a[2][4], b[8][2];
#pragma unroll
            for (int t = 0; t < 2; t++) {
                const float* ap = As + (wm + 16 * t + qr) * ASTR + k0 + qc;
                a[t][0] = __float_as_uint(ap[0]);
                a[t][1] = __float_as_uint(ap[8 * ASTR]);
                a[t][2] = __float_as_uint(ap[4]);
                a[t][3] = __float_as_uint(ap[8 * ASTR + 4]);
            }
#pragma unroll
            for (int n = 0; n < 8; n++) {
                const float* bp = Bs + (wn + 8 * n + qr) * ASTR + k0 + qc;
                b[n][0] = __float_as_uint(bp[0]);
                b[n][1] = __float_as_uint(bp[4]);
            }
#pragma unroll
            for (int t = 0; t < 2; t++)
#pragma unroll
                for (int n = 0; n < 8; n++)
                    asm volatile(
                        "mma.sync.aligned.m16n8k8.row.col.f32.tf32.tf32.f32 "
                        "{%0,%1,%2,%3}, {%4,%5,%6,%7}, {%8,%9}, {%0,%1,%2,%3};"
                        : "+f"(d[t][n][0]), "+f"(d[t][n][1]),
                          "+f"(d[t][n][2]), "+f"(d[t][n][3])
                        : "r"(a[t][0]), "r"(a[t][1]), "r"(a[t][2]), "r"(a[t][3]),
                          "r"(b[n][0]), "r"(b[n][1]));
        }
        __syncthreads();
    }

    // Epilogue
#pragma unroll
    for (int t = 0; t < 2; t++) {
        const int row = m0 + wm + 16 * t + qr;
#pragma unroll
        for (int n = 0; n < 8; n++) {
            const int col = n0 + wn + 8 * n + qc * 2;
            if (col < N) {
                *(float2*)&C[(size_t)row * N + col] =
                    make_float2(d[t][n][0], d[t][n][1]);
                *(float2*)&C[(size_t)(row + 8) * N + col] =
                    make_float2(d[t][n][2], d[t][n][3]);
            }
        }
    }
}

// ---------------------------------------------------------------------------
// RMSNorm (fp32 in, tf32-rounded out — feeds next GEMM as A operand)
// ---------------------------------------------------------------------------
__global__ __launch_bounds__(256)
void rmsnorm_kernel(const float* __restrict__ x, const float* __restrict__ w,
                    float* __restrict__ y, int n, int xstride) {
    const int row = blockIdx.x;
    const float* xr = x + (size_t)row * xstride;
    float ss = 0.f;
    for (int i = threadIdx.x; i < n; i += blockDim.x) {
        float v = xr[i];
        ss += v * v;
    }
    __shared__ float red[8];
#pragma unroll
    for (int off = 16; off > 0; off >>= 1) ss += __shfl_xor_sync(0xffffffffu, ss, off);
    if ((threadIdx.x & 31) == 0) red[threadIdx.x >> 5] = ss;
    __syncthreads();
    if (threadIdx.x < 8) {
        float v = red[threadIdx.x];
#pragma unroll
        for (int off = 4; off > 0; off >>= 1) v += __shfl_xor_sync(0x000000ffu, v, off);
        if (threadIdx.x == 0) red[0] = v;
    }
    __syncthreads();
    const float sc = rsqrtf(red[0] / (float)n + 1e-6f);
    float* yr = y + (size_t)row * n;
    for (int i = threadIdx.x; i < n; i += blockDim.x)
        yr[i] = tf32_rna(xr[i] * sc * w[i]);
}

// ---------------------------------------------------------------------------
// RoPE + per-head Q/K assembly
// ---------------------------------------------------------------------------
__global__ __launch_bounds__(160)
void assemble_kernel(const float* __restrict__ q, const float* __restrict__ kv,
                     const float* __restrict__ ckv, const float* __restrict__ freqs,
                     float* __restrict__ Q, float* __restrict__ K) {
    const int s = blockIdx.x, h = blockIdx.y, t = threadIdx.x;
    const size_t qbase  = (size_t)s * (NH_ * QK_) + (size_t)h * QK_;
    const size_t kvbase = (size_t)s * (NH_ * 256) + (size_t)h * 256;
    const size_t Qb = ((size_t)h * S_ + s) * QK_;
    if (t < 128) {
        Q[Qb + t] = q[qbase + t];
        K[Qb + t] = kv[kvbase + t];
    } else {
        const int i = t - 128;
        const float f  = freqs[(size_t)s * (DR_ / 2) + i];
        const float c  = cosf(f);
        const float sn = sinf(f);
        float xr = q[qbase + 128 + 2 * i];
        float xi = q[qbase + 128 + 2 * i + 1];
        Q[Qb + 128 + 2 * i]     = xr * c - xi * sn;
        Q[Qb + 128 + 2 * i + 1] = xr * sn + xi * c;
        float kr = ckv[(size_t)s * CKV_ + RKV_ + 2 * i];
        float ki = ckv[(size_t)s * CKV_ + RKV_ + 2 * i + 1];
        K[Qb + 128 + 2 * i]     = kr * c - ki * sn;
        K[Qb + 128 + 2 * i + 1] = kr * sn + ki * c;
    }
}

// ---------------------------------------------------------------------------
// Causal flash attention, fp32 (output tf32-rounded for o_proj)
// ---------------------------------------------------------------------------
#define KSTR 196
#define FLASH_SMEM ((64 * 192 + 64 * KSTR + 64 * 128 + 64 * 64) * 4)

__global__ __launch_bounds__(256)
void flash_kernel(const float* __restrict__ Q, const float* __restrict__ K,
                  const float* __restrict__ kv, float* __restrict__ O) {
    extern __shared__ float sm[];
    float* Qs = sm;
    float* Ks = Qs + 64 * 192;
    float* Vs = Ks + 64 * KSTR;
    float* Ps = Vs + 64 * 128;

    const int qt = blockIdx.x, h = blockIdx.y;
    const int tid = threadIdx.x;
    const int tx = tid & 15, ty = tid >> 4;
    const int q0 = qt * 64;
    const float scale = 0.07216878364870323f;

    const float* Qh = Q + ((size_t)h * S_ + q0) * QK_;
    for (int idx = tid; idx < 64 * 192; idx += 256) Qs[idx] = Qh[idx];

    float m_[4], l_[4], acc[4][8];
#pragma unroll
    for (int i = 0; i < 4; i++) {
        m_[i] = -1e30f; l_[i] = 0.f;
#pragma unroll
        for (int j = 0; j < 8; j++) acc[i][j] = 0.f;
    }

    for (int kt = 0; kt <= qt; kt++) {
        const int k0 = kt * 64;
        __syncthreads();
        const float* Kh = K + ((size_t)h * S_ + k0) * QK_;
        for (int idx = tid; idx < 64 * 192; idx += 256) {
            int r = idx / 192, c = idx - r * 192;
            Ks[r * KSTR + c] = Kh[idx];
        }
        for (int idx = tid; idx < 64 * 128; idx += 256) {
            int r = idx >> 7, c = idx & 127;
            Vs[idx] = kv[(size_t)(k0 + r) * (NH_ * 256) + (size_t)h * 256 + 128 + c];
        }
        __syncthreads();

        float s[4][4];
#pragma unroll
        for (int i = 0; i < 4; i++)
#pragma unroll
            for (int j = 0; j < 4; j++) s[i][j] = 0.f;

        for (int d = 0; d < 192; d += 4) {
            float4 a[4], b[4];
#pragma unroll
            for (int i = 0; i < 4; i++)
                a[i] = *(const float4*)&Qs[(ty + 16 * i) * 192 + d];
#pragma unroll
            for (int j = 0; j < 4; j++)
                b[j] = *(const float4*)&Ks[(tx + 16 * j) * KSTR + d];
#pragma unroll
            for (int i = 0; i < 4; i++)
#pragma unroll
                for (int j = 0; j < 4; j++)
                    s[i][j] += a[i].x * b[j].x + a[i].y * b[j].y
                             + a[i].z * b[j].z + a[i].w * b[j].w;
        }

        const bool diag = (kt == qt);
#pragma unroll
        for (int i = 0; i < 4; i++) {
            const int qg = q0 + ty + 16 * i;
            float rm = -1e30f;
#pragma unroll
            for (int j = 0; j < 4; j++) {
                float v = s[i][j] * scale;
                if (diag && (k0 + tx + 16 * j) > qg) v = -1e30f;
                s[i][j] = v;
                rm = fmaxf(rm, v);
            }
#pragma unroll
            for (int off = 8; off > 0; off >>= 1)
                rm = fmaxf(rm, __shfl_xor_sync(0xffffffffu, rm, off));
            const float mn   = fmaxf(m_[i], rm);
            const float corr = __expf(m_[i] - mn);
            float rs = 0.f;
#pragma unroll
            for (int j = 0; j < 4; j++) {
                float p = __expf(s[i][j] - mn);
                Ps[(ty + 16 * i) * 64 + tx + 16 * j] = p;
                rs += p;
            }
#pragma unroll
            for (int off = 8; off > 0; off >>= 1)
                rs += __shfl_xor_sync(0xffffffffu, rs, off);
            l_[i] = l_[i] * corr + rs;
            m_[i] = mn;
#pragma unroll
            for (int j = 0; j < 8; j++) acc[i][j] *= corr;
        }
        __syncthreads();

#pragma unroll 4
        for (int k = 0; k < 64; k++) {
            float4 v0 = *(const float4*)&Vs[(k << 7) + tx * 8];
            float4 v1 = *(const float4*)&Vs[(k << 7) + tx * 8 + 4];
#pragma unroll
            for (int i = 0; i < 4; i++) {
                float p = Ps[(ty + 16 * i) * 64 + k];
                acc[i][0] += p * v0.x; acc[i][1] += p * v0.y;
                acc[i][2] += p * v0.z; acc[i][3] += p * v0.w;
                acc[i][4] += p * v1.x; acc[i][5] += p * v1.y;
                acc[i][6] += p * v1.z; acc[i][7] += p * v1.w;
            }
        }
    }

#pragma unroll
    for (int i = 0; i < 4; i++) {
        const float inv = 1.f / l_[i];
        const int r = q0 + ty + 16 * i;
        float4 o0 = make_float4(tf32_rna(acc[i][0] * inv), tf32_rna(acc[i][1] * inv),
                                tf32_rna(acc[i][2] * inv), tf32_rna(acc[i][3] * inv));
        float4 o1 = make_float4(tf32_rna(acc[i][4] * inv), tf32_rna(acc[i][5] * inv),
                                tf32_rna(acc[i][6] * inv), tf32_rna(acc[i][7] * inv));
        const size_t ob = (size_t)r * (NH_ * DV_) + (size_t)h * DV_ + tx * 8;
        *(float4*)&O[ob]     = o0;
        *(float4*)&O[ob + 4] = o1;
    }
}

// ---------------------------------------------------------------------------
// kernel_launch
// ---------------------------------------------------------------------------
extern "C" void kernel_launch(void* const* d_in, const int* in_sizes, int n_in,
                              void* d_out, int out_size) {
    (void)in_sizes; (void)n_in; (void)out_size;
    const float* hs      = (const float*)d_in[0];
    const float* freqs   = (const float*)d_in[1];
    const float* q_a_w   = (const float*)d_in[2];
    const float* q_a_ln  = (const float*)d_in[3];
    const float* q_b_w   = (const float*)d_in[4];
    const float* kv_a_w  = (const float*)d_in[5];
    const float* kv_a_ln = (const float*)d_in[6];
    const float* kv_b_w  = (const float*)d_in[7];
    const float* o_w     = (const float*)d_in[8];
    float* out           = (float*)d_out;

    float *cq, *ckv, *qn, *kvn, *q, *kv, *Qp, *Kp, *attn;
    float *hsr, *qaw, *kvaw, *qbw, *kvbw, *ow;
    cudaGetSymbolAddress((void**)&cq,   g_cq);
    cudaGetSymbolAddress((void**)&ckv,  g_ckv);
    cudaGetSymbolAddress((void**)&qn,   g_qn);
    cudaGetSymbolAddress((void**)&kvn,  g_kvn);
    cudaGetSymbolAddress((void**)&q,    g_q);
    cudaGetSymbolAddress((void**)&kv,   g_kv);
    cudaGetSymbolAddress((void**)&Qp,   g_Q);
    cudaGetSymbolAddress((void**)&Kp,   g_K);
    cudaGetSymbolAddress((void**)&attn, g_attn);
    cudaGetSymbolAddress((void**)&hsr,  g_hsr);
    cudaGetSymbolAddress((void**)&qaw,  g_qaw);
    cudaGetSymbolAddress((void**)&kvaw, g_kvaw);
    cudaGetSymbolAddress((void**)&qbw,  g_qbw);
    cudaGetSymbolAddress((void**)&kvbw, g_kvbw);
    cudaGetSymbolAddress((void**)&ow,   g_ow);

    cudaFuncSetAttribute(gemm_mma, cudaFuncAttributeMaxDynamicSharedMemorySize, MGEMM_SMEM);
    cudaFuncSetAttribute(flash_kernel, cudaFuncAttributeMaxDynamicSharedMemorySize, FLASH_SMEM);

    const dim3 blk(256);
    const int mt = S_ / 128;   // 16

    // tf32 pre-rounding (operands of all GEMMs)
    round_tf32_kernel<<<1024, 256>>>(hs,     hsr,  S_ * H_);
    round_tf32_kernel<<<1024, 256>>>(q_a_w,  qaw,  RQ_ * H_);
    round_tf32_kernel<<<1024, 256>>>(kv_a_w, kvaw, CKV_ * H_);
    round_tf32_kernel<<<1024, 256>>>(q_b_w,  qbw,  NH_ * QK_ * RQ_);
    round_tf32_kernel<<<1024, 256>>>(kv_b_w, kvbw, NH_ * 256 * RKV_);
    round_tf32_kernel<<<1024, 256>>>(o_w,    ow,   H_ * NH_ * DV_);

    // down-projections
    gemm_mma<<<dim3(RQ_ / 128, mt), blk, MGEMM_SMEM>>>(hsr, qaw, cq, S_, RQ_, H_);
    gemm_mma<<<dim3((CKV_ + 127) / 128, mt), blk, MGEMM_SMEM>>>(hsr, kvaw, ckv, S_, CKV_, H_);

    // rmsnorms (tf32-rounded outputs)
    rmsnorm_kernel<<<S_, 256>>>(cq,  q_a_ln,  qn,  RQ_,  RQ_);
    rmsnorm_kernel<<<S_, 256>>>(ckv, kv_a_ln, kvn, RKV_, CKV_);

    // up-projections
    gemm_mma<<<dim3((NH_ * QK_) / 128, mt), blk, MGEMM_SMEM>>>(qn,  qbw,  q,  S_, NH_ * QK_, RQ_);
    gemm_mma<<<dim3((NH_ * 256) / 128, mt), blk, MGEMM_SMEM>>>(kvn, kvbw, kv, S_, NH_ * 256, RKV_);

    // RoPE + per-head assembly
    assemble_kernel<<<dim3(S_, NH_), 160>>>(q, kv, ckv, freqs, Qp, Kp);

    // causal flash attention (fp32 SIMT, rounded output)
    flash_kernel<<<dim3(S_ / 64, NH_), blk, FLASH_SMEM>>>(Qp, Kp, kv, attn);

    // output projection -> d_out
    gemm_mma<<<dim3(H_ / 128, mt), blk, MGEMM_SMEM>>>(attn, ow, out, S_, H_, NH_ * DV_);
}

// round 6
// speedup vs baseline: 3.4217x; 1.7972x over previous
#include <cuda_runtime.h>
#include <cuda_bf16.h>
#include <cstdint>
#include <cstddef>

// ---------------------------------------------------------------------------
// Problem constants (B=1)
// ---------------------------------------------------------------------------
#define S_   2048
#define H_   4096
#define NH_  32
#define DN_  128
#define DR_  64
#define DV_  128
#define QK_  192      // DN + DR
#define RQ_  1536
#define RKV_ 512
#define CKV_ 576      // RKV + DR

// ---------------------------------------------------------------------------
// Device scratch
// ---------------------------------------------------------------------------
__device__ float g_cq  [S_ * RQ_];
__device__ float g_ckv [S_ * CKV_];
__device__ float g_qn  [S_ * RQ_];
__device__ float g_kvn [S_ * RKV_];
__device__ float g_q   [S_ * (NH_ * QK_)];
__device__ float g_kv  [S_ * (NH_ * 256)];
__device__ float g_Q   [NH_ * S_ * QK_];
__device__ float g_K   [NH_ * S_ * QK_];
__device__ float g_attn[S_ * (NH_ * DV_)];

// tf32-rounded operand copies
__device__ float g_hsr  [S_ * H_];
__device__ float g_qaw  [RQ_ * H_];
__device__ float g_kvaw [CKV_ * H_];
__device__ float g_qbw  [NH_ * QK_ * RQ_];
__device__ float g_kvbw [NH_ * 256 * RKV_];
__device__ float g_ow   [H_ * NH_ * DV_];

// ---------------------------------------------------------------------------
// Helpers
// ---------------------------------------------------------------------------
__device__ __forceinline__ float tf32_rna(float x) {
    uint32_t r;
    asm("cvt.rna.tf32.f32 %0, %1;" : "=r"(r) : "f"(x));
    return __uint_as_float(r);
}

__device__ __forceinline__ void cp_async16(uint32_t dst, const void* src, bool pred) {
    int sz = pred ? 16 : 0;
    asm volatile("cp.async.cg.shared.global [%0], [%1], 16, %2;"
                 :: "r"(dst), "l"(src), "r"(sz));
}
__device__ __forceinline__ void cp_commit() {
    asm volatile("cp.async.commit_group;" ::: "memory");
}
template <int N> __device__ __forceinline__ void cp_wait() {
    asm volatile("cp.async.wait_group %0;" :: "n"(N) : "memory");
}

__device__ __forceinline__ uint32_t smem_u32(const void* p) {
    uint32_t a;
    asm("{ .reg .u64 t; cvta.to.shared.u64 t, %1; cvt.u32.u64 %0, t; }"
        : "=r"(a) : "l"(p));
    return a;
}

#define MMA_TF32(d, a, b)                                                     \
    asm volatile(                                                             \
        "mma.sync.aligned.m16n8k8.row.col.f32.tf32.tf32.f32 "                 \
        "{%0,%1,%2,%3}, {%4,%5,%6,%7}, {%8,%9}, {%0,%1,%2,%3};"               \
        : "+f"((d)[0]), "+f"((d)[1]), "+f"((d)[2]), "+f"((d)[3])              \
        : "r"((a)[0]), "r"((a)[1]), "r"((a)[2]), "r"((a)[3]),                 \
          "r"((b)[0]), "r"((b)[1]))

// ---------------------------------------------------------------------------
// Elementwise tf32 rounding
// ---------------------------------------------------------------------------
__global__ __launch_bounds__(256)
void round_tf32_kernel(const float* __restrict__ x, float* __restrict__ y, int n) {
    int i = (blockIdx.x * blockDim.x + threadIdx.x) * 4;
    const int stride = gridDim.x * blockDim.x * 4;
    for (; i < n; i += stride) {
        float4 v = *(const float4*)(x + i);
        v.x = tf32_rna(v.x); v.y = tf32_rna(v.y);
        v.z = tf32_rna(v.z); v.w = tf32_rna(v.w);
        *(float4*)(y + i) = v;
    }
}

// ---------------------------------------------------------------------------
// mma.sync tf32 GEMM:  C[M,N] = A[M,K] @ B[N,K]^T
// CTA 128x128x32, 8 warps (4 x 2), warp tile 32x64, 3-stage cp.async.
// ---------------------------------------------------------------------------
#define ASTR 36
#define MSTAGE_BYTES (2 * 128 * ASTR * 4)
#define MSTAGES 3
#define MGEMM_SMEM (MSTAGES * MSTAGE_BYTES)

__global__ __launch_bounds__(256)
void gemm_mma(const float* __restrict__ A, const float* __restrict__ B,
              float* __restrict__ C, int M, int N, int K) {
    extern __shared__ char smem[];
    const uint32_t sb = smem_u32(smem);
    const int tid  = threadIdx.x;
    const int wid  = tid >> 5;
    const int lane = tid & 31;
    const int qr = lane >> 2;
    const int qc = lane & 3;
    const int wm = (wid & 3) * 32;
    const int wn = (wid >> 2) * 64;
    const int m0 = blockIdx.y * 128;
    const int n0 = blockIdx.x * 128;

    const int niter = K / 32;

    auto load_stage = [&](int it) {
        const int s = it % MSTAGES;
        const uint32_t abase = sb + s * MSTAGE_BYTES;
        const uint32_t bbase = abase + 128 * ASTR * 4;
        const int k0 = it * 32;
#pragma unroll
        for (int j = 0; j < 4; j++) {
            int idx = tid + 256 * j;
            int r = idx >> 3, c4 = idx & 7;
            cp_async16(abase + (r * ASTR + c4 * 4) * 4,
                       A + (size_t)(m0 + r) * K + k0 + c4 * 4, true);
        }
#pragma unroll
        for (int j = 0; j < 4; j++) {
            int idx = tid + 256 * j;
            int r = idx >> 3, c4 = idx & 7;
            bool ok = (n0 + r) < N;
            const float* src = B + (size_t)(n0 + (ok ? r : 0)) * K + k0 + c4 * 4;
            cp_async16(bbase + (r * ASTR + c4 * 4) * 4, src, ok);
        }
        cp_commit();
    };

    float d[2][8][4];
#pragma unroll
    for (int t = 0; t < 2; t++)
#pragma unroll
        for (int n = 0; n < 8; n++)
#pragma unroll
            for (int c = 0; c < 4; c++) d[t][n][c] = 0.f;

    load_stage(0);
    load_stage(1);

    for (int it = 0; it < niter; it++) {
        cp_wait<1>();
        __syncthreads();

        if (it + 2 < niter) load_stage(it + 2);

        const int s = it % MSTAGES;
        const float* As = (const float*)(smem + s * MSTAGE_BYTES);
        const float* Bs = As + 128 * ASTR;

#pragma unroll
        for (int k8 = 0; k8 < 4; k8++) {
            const int k0 = k8 * 8;
            uint32_t a[2][4], b[8][2];
#pragma unroll
            for (int t = 0; t < 2; t++) {
                const float* ap = As + (wm + 16 * t + qr) * ASTR + k0 + qc;
                a[t][0] = __float_as_uint(ap[0]);
                a[t][1] = __float_as_uint(ap[8 * ASTR]);
                a[t][2] = __float_as_uint(ap[4]);
                a[t][3] = __float_as_uint(ap[8 * ASTR + 4]);
            }
#pragma unroll
            for (int n = 0; n < 8; n++) {
                const float* bp = Bs + (wn + 8 * n + qr) * ASTR + k0 + qc;
                b[n][0] = __float_as_uint(bp[0]);
                b[n][1] = __float_as_uint(bp[4]);
            }
#pragma unroll
            for (int t = 0; t < 2; t++)
#pragma unroll
                for (int n = 0; n < 8; n++)
                    MMA_TF32(d[t][n], a[t], b[n]);
        }
        __syncthreads();
    }

#pragma unroll
    for (int t = 0; t < 2; t++) {
        const int row = m0 + wm + 16 * t + qr;
#pragma unroll
        for (int n = 0; n < 8; n++) {
            const int col = n0 + wn + 8 * n + qc * 2;
            if (col < N) {
                *(float2*)&C[(size_t)row * N + col] =
                    make_float2(d[t][n][0], d[t][n][1]);
                *(float2*)&C[(size_t)(row + 8) * N + col] =
                    make_float2(d[t][n][2], d[t][n][3]);
            }
        }
    }
}

// ---------------------------------------------------------------------------
// RMSNorm (tf32-rounded out)
// ---------------------------------------------------------------------------
__global__ __launch_bounds__(256)
void rmsnorm_kernel(const float* __restrict__ x, const float* __restrict__ w,
                    float* __restrict__ y, int n, int xstride) {
    const int row = blockIdx.x;
    const float* xr = x + (size_t)row * xstride;
    float ss = 0.f;
    for (int i = threadIdx.x; i < n; i += blockDim.x) {
        float v = xr[i];
        ss += v * v;
    }
    __shared__ float red[8];
#pragma unroll
    for (int off = 16; off > 0; off >>= 1) ss += __shfl_xor_sync(0xffffffffu, ss, off);
    if ((threadIdx.x & 31) == 0) red[threadIdx.x >> 5] = ss;
    __syncthreads();
    if (threadIdx.x < 8) {
        float v = red[threadIdx.x];
#pragma unroll
        for (int off = 4; off > 0; off >>= 1) v += __shfl_xor_sync(0x000000ffu, v, off);
        if (threadIdx.x == 0) red[0] = v;
    }
    __syncthreads();
    const float sc = rsqrtf(red[0] / (float)n + 1e-6f);
    float* yr = y + (size_t)row * n;
    for (int i = threadIdx.x; i < n; i += blockDim.x)
        yr[i] = tf32_rna(xr[i] * sc * w[i]);
}

// ---------------------------------------------------------------------------
// RoPE + per-head Q/K assembly (outputs tf32-rounded: flash mma operands)
// ---------------------------------------------------------------------------
__global__ __launch_bounds__(160)
void assemble_kernel(const float* __restrict__ q, const float* __restrict__ kv,
                     const float* __restrict__ ckv, const float* __restrict__ freqs,
                     float* __restrict__ Q, float* __restrict__ K) {
    const int s = blockIdx.x, h = blockIdx.y, t = threadIdx.x;
    const size_t qbase  = (size_t)s * (NH_ * QK_) + (size_t)h * QK_;
    const size_t kvbase = (size_t)s * (NH_ * 256) + (size_t)h * 256;
    const size_t Qb = ((size_t)h * S_ + s) * QK_;
    if (t < 128) {
        Q[Qb + t] = tf32_rna(q[qbase + t]);
        K[Qb + t] = tf32_rna(kv[kvbase + t]);
    } else {
        const int i = t - 128;
        const float f  = freqs[(size_t)s * (DR_ / 2) + i];
        const float c  = cosf(f);
        const float sn = sinf(f);
        float xr = q[qbase + 128 + 2 * i];
        float xi = q[qbase + 128 + 2 * i + 1];
        Q[Qb + 128 + 2 * i]     = tf32_rna(xr * c - xi * sn);
        Q[Qb + 128 + 2 * i + 1] = tf32_rna(xr * sn + xi * c);
        float kr = ckv[(size_t)s * CKV_ + RKV_ + 2 * i];
        float ki = ckv[(size_t)s * CKV_ + RKV_ + 2 * i + 1];
        K[Qb + 128 + 2 * i]     = tf32_rna(kr * c - ki * sn);
        K[Qb + 128 + 2 * i + 1] = tf32_rna(kr * sn + ki * c);
    }
}

// ---------------------------------------------------------------------------
// Causal flash attention, tf32 mma.sync.
// BQ = BK = 64. 8 warps: 4 (M) x 2 (N).
// S-phase warp tile 16x32, PV-phase warp tile 16x64.
// smem strides: Q/K 196 (=4 mod 32), V 136 (=8 mod 32), P 68 (=4 mod 32)
//   -> all fragment LDS conflict-free.
// ---------------------------------------------------------------------------
#define QSTR 196
#define VSTR 136
#define PSTR 68
#define F_QS 0
#define F_KS (64 * QSTR)
#define F_VS (F_KS + 64 * QSTR)
#define F_PS (F_VS + 64 * VSTR)
#define F_RD (F_PS + 64 * PSTR)              // red[2][64][2]
#define FLASH_SMEM ((F_RD + 256) * 4)        // 153.6 KB

__global__ __launch_bounds__(256)
void flash_kernel(const float* __restrict__ Q, const float* __restrict__ K,
                  const float* __restrict__ kv, float* __restrict__ O) {
    extern __shared__ float sm[];
    float* Qs = sm + F_QS;
    float* Ks = sm + F_KS;
    float* Vs = sm + F_VS;
    float* Ps = sm + F_PS;
    float* RM = sm + F_RD;          // [64][2] partial max
    float* RS = sm + F_RD + 128;    // [64][2] partial sum

    const int qt = gridDim.x - 1 - blockIdx.x;   // large tiles first
    const int h  = blockIdx.y;
    const int tid = threadIdx.x;
    const int wid = tid >> 5, lane = tid & 31;
    const int qr = lane >> 2, qc = lane & 3;
    const int wm  = (wid & 3) * 16;          // warp M offset (rows)
    const int wns = (wid >> 2) * 32;         // warp N offset, S phase
    const int wnv = (wid >> 2) * 64;         // warp N offset, PV phase
    const int whalf = wid >> 2;              // 0/1 column-warp id
    const int q0 = qt * 64;
    const float scale = 0.07216878364870323f;   // 1/sqrt(192)

    // load Q tile (stays for the block)
    const float* Qh = Q + ((size_t)h * S_ + q0) * QK_;
    for (int idx = tid; idx < 64 * 48; idx += 256) {     // 3072 float4
        int r = idx / 48, c4 = idx % 48;
        float4 v = *(const float4*)(Qh + r * QK_ + c4 * 4);
        *(float4*)&Qs[r * QSTR + c4 * 4] = v;
    }

    const int r0 = wm + qr;          // local row of first acc row
    float m0v = -1e30f, m1v = -1e30f, l0v = 0.f, l1v = 0.f;
    float od[8][4];
#pragma unroll
    for (int n = 0; n < 8; n++)
#pragma unroll
        for (int c = 0; c < 4; c++) od[n][c] = 0.f;

    const float* kvh = kv + (size_t)h * 256 + 128;

    for (int kt = 0; kt <= qt; kt++) {
        const int k0 = kt * 64;
        __syncthreads();   // prev iter reads of Ks/Vs/Ps done

        const float* Kh = K + ((size_t)h * S_ + k0) * QK_;
        for (int idx = tid; idx < 64 * 48; idx += 256) {
            int r = idx / 48, c4 = idx % 48;
            float4 v = *(const float4*)(Kh + r * QK_ + c4 * 4);
            *(float4*)&Ks[r * QSTR + c4 * 4] = v;
        }
        for (int idx = tid; idx < 64 * 32; idx += 256) {  // V: 2048 float4
            int r = idx >> 5, c4 = idx & 31;
            float4 v = *(const float4*)(kvh + (size_t)(k0 + r) * (NH_ * 256) + c4 * 4);
            v.x = tf32_rna(v.x); v.y = tf32_rna(v.y);
            v.z = tf32_rna(v.z); v.w = tf32_rna(v.w);
            *(float4*)&Vs[r * VSTR + c4 * 4] = v;
        }
        __syncthreads();

        // ---- S = Q @ K^T (warp tile 16 x 32) ----
        float sd[4][4];
#pragma unroll
        for (int n = 0; n < 4; n++)
#pragma unroll
            for (int c = 0; c < 4; c++) sd[n][c] = 0.f;

#pragma unroll
        for (int k8 = 0; k8 < 24; k8++) {
            const int kk = k8 * 8;
            uint32_t a[4], b[4][2];
            const float* ap = Qs + (wm + qr) * QSTR + kk + qc;
            a[0] = __float_as_uint(ap[0]);
            a[1] = __float_as_uint(ap[8 * QSTR]);
            a[2] = __float_as_uint(ap[4]);
            a[3] = __float_as_uint(ap[8 * QSTR + 4]);
#pragma unroll
            for (int n = 0; n < 4; n++) {
                const float* bp = Ks + (wns + 8 * n + qr) * QSTR + kk + qc;
                b[n][0] = __float_as_uint(bp[0]);
                b[n][1] = __float_as_uint(bp[4]);
            }
#pragma unroll
            for (int n = 0; n < 4; n++) MMA_TF32(sd[n], a, b[n]);
        }

        // ---- scale + causal mask + partial row max ----
        const bool diag = (kt == qt);
        float pm0 = -1e30f, pm1 = -1e30f;
#pragma unroll
        for (int n = 0; n < 4; n++) {
            const int colb = k0 + wns + 8 * n + 2 * qc;
#pragma unroll
            for (int c = 0; c < 4; c++) {
                float v = sd[n][c] * scale;
                if (diag) {
                    const int row = q0 + r0 + (c >> 1) * 8;
                    if (colb + (c & 1) > row) v = -1e30f;
                }
                sd[n][c] = v;
                if (c < 2) pm0 = fmaxf(pm0, v); else pm1 = fmaxf(pm1, v);
            }
        }
#pragma unroll
        for (int off = 1; off < 4; off <<= 1) {
            pm0 = fmaxf(pm0, __shfl_xor_sync(0xffffffffu, pm0, off));
            pm1 = fmaxf(pm1, __shfl_xor_sync(0xffffffffu, pm1, off));
        }
        if (qc == 0) {
            RM[r0 * 2 + whalf]       = pm0;
            RM[(r0 + 8) * 2 + whalf] = pm1;
        }
        __syncthreads();

        // ---- combine max, exp, write P, partial sums, rescale acc ----
        const float rm0 = fmaxf(RM[r0 * 2], RM[r0 * 2 + 1]);
        const float rm1 = fmaxf(RM[(r0 + 8) * 2], RM[(r0 + 8) * 2 + 1]);
        const float mn0 = fmaxf(m0v, rm0);
        const float mn1 = fmaxf(m1v, rm1);
        const float co0 = __expf(m0v - mn0);
        const float co1 = __expf(m1v - mn1);
        float ps0 = 0.f, ps1 = 0.f;
#pragma unroll
        for (int n = 0; n < 4; n++) {
            const int colb = wns + 8 * n + 2 * qc;
            float p0 = tf32_rna(__expf(sd[n][0] - mn0));
            float p1 = tf32_rna(__expf(sd[n][1] - mn0));
            float p2 = tf32_rna(__expf(sd[n][2] - mn1));
            float p3 = tf32_rna(__expf(sd[n][3] - mn1));
            Ps[r0 * PSTR + colb]           = p0;
            Ps[r0 * PSTR + colb + 1]       = p1;
            Ps[(r0 + 8) * PSTR + colb]     = p2;
            Ps[(r0 + 8) * PSTR + colb + 1] = p3;
            ps0 += p0 + p1;
            ps1 += p2 + p3;
        }
#pragma unroll
        for (int off = 1; off < 4; off <<= 1) {
            ps0 += __shfl_xor_sync(0xffffffffu, ps0, off);
            ps1 += __shfl_xor_sync(0xffffffffu, ps1, off);
        }
        if (qc == 0) {
            RS[r0 * 2 + whalf]       = ps0;
            RS[(r0 + 8) * 2 + whalf] = ps1;
        }
#pragma unroll
        for (int n = 0; n < 8; n++) {
            od[n][0] *= co0; od[n][1] *= co0;
            od[n][2] *= co1; od[n][3] *= co1;
        }
        m0v = mn0; m1v = mn1;
        __syncthreads();

        l0v = l0v * co0 + RS[r0 * 2] + RS[r0 * 2 + 1];
        l1v = l1v * co1 + RS[(r0 + 8) * 2] + RS[(r0 + 8) * 2 + 1];

        // ---- acc += P @ V (warp tile 16 x 64) ----
#pragma unroll
        for (int k8 = 0; k8 < 8; k8++) {
            const int kk = k8 * 8;
            uint32_t a[4], b[8][2];
            const float* ap = Ps + (wm + qr) * PSTR + kk + qc;
            a[0] = __float_as_uint(ap[0]);
            a[1] = __float_as_uint(ap[8 * PSTR]);
            a[2] = __float_as_uint(ap[4]);
            a[3] = __float_as_uint(ap[8 * PSTR + 4]);
#pragma unroll
            for (int n = 0; n < 8; n++) {
                const float* bp = Vs + (kk + qc) * VSTR + wnv + 8 * n + qr;
                b[n][0] = __float_as_uint(bp[0]);
                b[n][1] = __float_as_uint(bp[4 * VSTR]);
            }
#pragma unroll
            for (int n = 0; n < 8; n++) MMA_TF32(od[n], a, b[n]);
        }
    }

    // ---- epilogue ----
    const float i0 = 1.f / l0v, i1 = 1.f / l1v;
    const int grow0 = q0 + r0, grow1 = q0 + r0 + 8;
#pragma unroll
    for (int n = 0; n < 8; n++) {
        const int col = wnv + 8 * n + 2 * qc;
        const size_t b0 = (size_t)grow0 * (NH_ * DV_) + (size_t)h * DV_ + col;
        const size_t b1 = (size_t)grow1 * (NH_ * DV_) + (size_t)h * DV_ + col;
        O[b0]     = tf32_rna(od[n][0] * i0);
        O[b0 + 1] = tf32_rna(od[n][1] * i0);
        O[b1]     = tf32_rna(od[n][2] * i1);
        O[b1 + 1] = tf32_rna(od[n][3] * i1);
    }
}

// ---------------------------------------------------------------------------
// kernel_launch
// ---------------------------------------------------------------------------
extern "C" void kernel_launch(void* const* d_in, const int* in_sizes, int n_in,
                              void* d_out, int out_size) {
    (void)in_sizes; (void)n_in; (void)out_size;
    const float* hs      = (const float*)d_in[0];
    const float* freqs   = (const float*)d_in[1];
    const float* q_a_w   = (const float*)d_in[2];
    const float* q_a_ln  = (const float*)d_in[3];
    const float* q_b_w   = (const float*)d_in[4];
    const float* kv_a_w  = (const float*)d_in[5];
    const float* kv_a_ln = (const float*)d_in[6];
    const float* kv_b_w  = (const float*)d_in[7];
    const float* o_w     = (const float*)d_in[8];
    float* out           = (float*)d_out;

    float *cq, *ckv, *qn, *kvn, *q, *kv, *Qp, *Kp, *attn;
    float *hsr, *qaw, *kvaw, *qbw, *kvbw, *ow;
    cudaGetSymbolAddress((void**)&cq,   g_cq);
    cudaGetSymbolAddress((void**)&ckv,  g_ckv);
    cudaGetSymbolAddress((void**)&qn,   g_qn);
    cudaGetSymbolAddress((void**)&kvn,  g_kvn);
    cudaGetSymbolAddress((void**)&q,    g_q);
    cudaGetSymbolAddress((void**)&kv,   g_kv);
    cudaGetSymbolAddress((void**)&Qp,   g_Q);
    cudaGetSymbolAddress((void**)&Kp,   g_K);
    cudaGetSymbolAddress((void**)&attn, g_attn);
    cudaGetSymbolAddress((void**)&hsr,  g_hsr);
    cudaGetSymbolAddress((void**)&qaw,  g_qaw);
    cudaGetSymbolAddress((void**)&kvaw, g_kvaw);
    cudaGetSymbolAddress((void**)&qbw,  g_qbw);
    cudaGetSymbolAddress((void**)&kvbw, g_kvbw);
    cudaGetSymbolAddress((void**)&ow,   g_ow);

    cudaFuncSetAttribute(gemm_mma, cudaFuncAttributeMaxDynamicSharedMemorySize, MGEMM_SMEM);
    cudaFuncSetAttribute(flash_kernel, cudaFuncAttributeMaxDynamicSharedMemorySize, FLASH_SMEM);

    const dim3 blk(256);
    const int mt = S_ / 128;   // 16

    // tf32 pre-rounding
    round_tf32_kernel<<<1024, 256>>>(hs,     hsr,  S_ * H_);
    round_tf32_kernel<<<1024, 256>>>(q_a_w,  qaw,  RQ_ * H_);
    round_tf32_kernel<<<1024, 256>>>(kv_a_w, kvaw, CKV_ * H_);
    round_tf32_kernel<<<1024, 256>>>(q_b_w,  qbw,  NH_ * QK_ * RQ_);
    round_tf32_kernel<<<1024, 256>>>(kv_b_w, kvbw, NH_ * 256 * RKV_);
    round_tf32_kernel<<<1024, 256>>>(o_w,    ow,   H_ * NH_ * DV_);

    // down-projections
    gemm_mma<<<dim3(RQ_ / 128, mt), blk, MGEMM_SMEM>>>(hsr, qaw, cq, S_, RQ_, H_);
    gemm_mma<<<dim3((CKV_ + 127) / 128, mt), blk, MGEMM_SMEM>>>(hsr, kvaw, ckv, S_, CKV_, H_);

    // rmsnorms
    rmsnorm_kernel<<<S_, 256>>>(cq,  q_a_ln,  qn,  RQ_,  RQ_);
    rmsnorm_kernel<<<S_, 256>>>(ckv, kv_a_ln, kvn, RKV_, CKV_);

    // up-projections
    gemm_mma<<<dim3((NH_ * QK_) / 128, mt), blk, MGEMM_SMEM>>>(qn,  qbw,  q,  S_, NH_ * QK_, RQ_);
    gemm_mma<<<dim3((NH_ * 256) / 128, mt), blk, MGEMM_SMEM>>>(kvn, kvbw, kv, S_, NH_ * 256, RKV_);

    // RoPE + per-head assembly (tf32-rounded outputs)
    assemble_kernel<<<dim3(S_, NH_), 160>>>(q, kv, ckv, freqs, Qp, Kp);

    // causal flash attention (tf32 mma)
    flash_kernel<<<dim3(S_ / 64, NH_), blk, FLASH_SMEM>>>(Qp, Kp, kv, attn);

    // output projection -> d_out
    gemm_mma<<<dim3(H_ / 128, mt), blk, MGEMM_SMEM>>>(attn, ow, out, S_, H_, NH_ * DV_);
}